// round 8
// baseline (speedup 1.0000x reference)
#include <cuda_runtime.h>
#include <cuda_fp16.h>
#include <cstdint>

#define CC       64
#define OUTC     256
#define HWN      4096
#define NCHUNK   65
#define PTILE    128
#define NTHREADS 512
#define WSTRIDE  (OUTC*CC)          // 16384 halves per weight chunk

// smem byte offsets
#define SM_XS    0                   // 64 x 128 fp32 = 32KB
#define SM_A     32768               // 2 stages x 32KB  ([256 o][64 k] f16, 128B rows)
#define SM_B     (32768 + 65536)     // 2 stages x 16KB  ([128 p][64 k] f16, 128B rows)
#define SM_TOTAL (SM_B + 32768)      // 128KB

#define SWZ(o) ((o) ^ (((o) >> 3) & 0x70))

__device__ __align__(16) __half g_Wh[NCHUNK * WSTRIDE];   // 2.1MB prepared f16 weights

__device__ __forceinline__ uint32_t s2u(const void* p) {
    uint32_t a;
    asm("{ .reg .u64 t; cvta.to.shared.u64 t, %1; cvt.u32.u64 %0, t; }" : "=r"(a) : "l"(p));
    return a;
}
__device__ __forceinline__ void cp16(uint32_t dst, const void* src) {
    asm volatile("cp.async.cg.shared.global [%0], [%1], 16;" :: "r"(dst), "l"(src) : "memory");
}
#define CP_COMMIT() asm volatile("cp.async.commit_group;" ::: "memory")
#define CP_WAIT0()  asm volatile("cp.async.wait_group 0;" ::: "memory")

__device__ __forceinline__ void ldsm_x4(uint32_t a, uint32_t& r0, uint32_t& r1, uint32_t& r2, uint32_t& r3) {
    asm volatile("ldmatrix.sync.aligned.m8n8.x4.shared.b16 {%0,%1,%2,%3}, [%4];"
                 : "=r"(r0), "=r"(r1), "=r"(r2), "=r"(r3) : "r"(a));
}
__device__ __forceinline__ void ldsm_x2(uint32_t a, uint32_t& r0, uint32_t& r1) {
    asm volatile("ldmatrix.sync.aligned.m8n8.x2.shared.b16 {%0,%1}, [%2];"
                 : "=r"(r0), "=r"(r1) : "r"(a));
}
__device__ __forceinline__ void mma16816(float* d, const uint32_t* a, const uint32_t* b) {
    asm volatile("mma.sync.aligned.m16n8k16.row.col.f32.f16.f16.f32 "
                 "{%0,%1,%2,%3}, {%4,%5,%6,%7}, {%8,%9}, {%0,%1,%2,%3};"
                 : "+f"(d[0]), "+f"(d[1]), "+f"(d[2]), "+f"(d[3])
                 : "r"(a[0]), "r"(a[1]), "r"(a[2]), "r"(a[3]), "r"(b[0]), "r"(b[1]));
}

// ---- weight prep: fc_w fp32 [256 x 2144] -> g_Wh f16 [chunk][o][k], zero below diag ----
__global__ void prep_kernel(const float* __restrict__ fc_w) {
    int idx = blockIdx.x * blockDim.x + threadIdx.x;   // exactly 65*16384
    int chunk = idx >> 14;
    int rem = idx & 16383;
    int o = rem >> 6;
    int k = rem & 63;
    float v = 0.0f;
    if (chunk == 64) {
        v = fc_w[o * 2144 + k];                                // linear part
    } else if (k >= chunk) {
        int off = 64 + chunk * 64 - (chunk * (chunk - 1)) / 2 + (k - chunk);
        v = fc_w[o * 2144 + off];                              // triu(i=chunk, j=k)
    }
    g_Wh[idx] = __float2half_rn(v);
}

__device__ __forceinline__ void load_A(uint32_t dstStage, int chunk, int tid) {
    const int ks16 = (chunk < 64) ? (chunk >> 4) : 0;
    const int o = tid >> 1, h = tid & 1;
    const __half* src = g_Wh + (size_t)chunk * WSTRIDE + o * 64 + h * 8;
#pragma unroll
    for (int kt = 0; kt < 4; kt++) {
        if (kt >= ks16) {
            uint32_t d = dstStage + SWZ((uint32_t)(o * 128 + kt * 32 + h * 16));
            cp16(d, src + kt * 16);
        }
    }
}

// ---- main: 256 CTAs x 512 threads; CTA = 256 outputs x 128 pixels ----
__global__ void __launch_bounds__(NTHREADS, 1)
quad_main(const float* __restrict__ x, float* __restrict__ out) {
    extern __shared__ __align__(1024) char smem[];
    const uint32_t sb = s2u(smem);
    const int tid = threadIdx.x;
    const int lane = tid & 31;
    const int wid = tid >> 5;
    const int mw = wid & 3;          // output  64-block
    const int nw = wid >> 2;         // pixel   32-block

    const int bidx = blockIdx.x >> 5;          // batch
    const int hw0  = (blockIdx.x & 31) << 7;   // pixel tile base (128)

    float* xs = (float*)(smem + SM_XS);        // [c][p] fp32

    // prefetch A chunk 0
    load_A(sb + SM_A, 0, tid);
    CP_COMMIT();

    // load x tile [64][128]
    {
        const float4* xg = (const float4*)(x + (size_t)bidx * CC * HWN + hw0);
#pragma unroll
        for (int j = 0; j < 4; j++) {
            int idx = tid + j * NTHREADS;       // 0..2047
            int c = idx >> 5, p4 = idx & 31;
            ((float4*)xs)[c * 32 + p4] = xg[(size_t)c * (HWN / 4) + p4];
        }
    }
    __syncthreads();

    // lane-derived ldmatrix offsets
    const int arow = (lane & 7) + ((lane >> 3) & 1) * 8;   // row within 16
    const int acol = ((lane >> 4) & 1) * 16;               // byte offset (hi 8 halves)
    const int brow = lane & 7;
    const int bcol = ((lane >> 3) & 1) * 16;

    float acc[4][4][4];
#pragma unroll
    for (int a = 0; a < 4; a++)
#pragma unroll
        for (int b = 0; b < 4; b++)
#pragma unroll
            for (int c = 0; c < 4; c++) acc[a][b][c] = 0.0f;

    const int bp  = tid >> 2;       // producer pixel
    const int bks = tid & 3;        // producer k-block

#pragma unroll 1
    for (int chunk = 0; chunk < NCHUNK; chunk++) {
        const int s = chunk & 1;
        const int ks16 = (chunk < 64) ? (chunk >> 4) : 0;

        // ---- produce B[s]: [p][k] f16 products ----
        if (bks >= ks16) {
            const float xi = (chunk < 64) ? xs[chunk * PTILE + bp] : 1.0f;
            __half2 h[8];
#pragma unroll
            for (int j = 0; j < 8; j++) {
                float a0 = xs[(bks * 16 + 2 * j) * PTILE + bp];
                float a1 = xs[(bks * 16 + 2 * j + 1) * PTILE + bp];
                h[j] = __floats2half2_rn(xi * a0, xi * a1);
            }
            char* bbase = smem + SM_B + s * 16384;
            const uint32_t ro = (uint32_t)bp * 128 + bks * 32;
            *(uint4*)(bbase + SWZ(ro))      = *(uint4*)&h[0];
            *(uint4*)(bbase + SWZ(ro + 16)) = *(uint4*)&h[4];
        }

        CP_WAIT0();        // A[chunk] arrived
        __syncthreads();   // A[s] + B[s] visible to all

        if (chunk + 1 < NCHUNK) {        // prefetch next A (overlaps mma below)
            load_A(sb + SM_A + (s ^ 1) * 32768, chunk + 1, tid);
            CP_COMMIT();
        }

        const uint32_t aA = sb + SM_A + s * 32768;
        const uint32_t aB = sb + SM_B + s * 16384;

#pragma unroll
        for (int kt = 0; kt < 4; kt++) {
            if (kt >= ks16) {
                uint32_t af[4][4];
#pragma unroll
                for (int mt = 0; mt < 4; mt++) {
                    uint32_t addr = aA + SWZ((uint32_t)((mw * 64 + mt * 16 + arow) * 128 + kt * 32 + acol));
                    ldsm_x4(addr, af[mt][0], af[mt][1], af[mt][2], af[mt][3]);
                }
                uint32_t bf[4][2];
#pragma unroll
                for (int nt = 0; nt < 4; nt++) {
                    uint32_t addr = aB + SWZ((uint32_t)((nw * 32 + nt * 8 + brow) * 128 + kt * 32 + bcol));
                    ldsm_x2(addr, bf[nt][0], bf[nt][1]);
                }
#pragma unroll
                for (int mt = 0; mt < 4; mt++)
#pragma unroll
                    for (int nt = 0; nt < 4; nt++)
                        mma16816(acc[mt][nt], af[mt], bf[nt]);
            }
        }
    }

    // ---- epilogue: fp32 accumulators -> out[b][o][hw] ----
#pragma unroll
    for (int mt = 0; mt < 4; mt++) {
#pragma unroll
        for (int nt = 0; nt < 4; nt++) {
            const int o = mw * 64 + mt * 16 + (lane >> 2);
            const int p = nw * 32 + nt * 8 + (lane & 3) * 2;
            float* op = out + ((size_t)bidx * OUTC + o) * HWN + hw0 + p;
            float2 v0 = make_float2(acc[mt][nt][0], acc[mt][nt][1]);
            float2 v1 = make_float2(acc[mt][nt][2], acc[mt][nt][3]);
            *(float2*)op = v0;
            *(float2*)(op + 8 * HWN) = v1;
        }
    }
}

extern "C" void kernel_launch(void* const* d_in, const int* in_sizes, int n_in,
                              void* d_out, int out_size) {
    const float* x    = (const float*)d_in[0];
    const float* fc_w = (const float*)d_in[1];
    float* out = (float*)d_out;

    cudaFuncSetAttribute(quad_main, cudaFuncAttributeMaxDynamicSharedMemorySize, SM_TOTAL);

    prep_kernel<<<1040, 1024>>>(fc_w);            // 65*16384 threads exactly
    quad_main<<<256, NTHREADS, SM_TOTAL>>>(x, out);
}

// round 10
// speedup vs baseline: 1.1807x; 1.1807x over previous
#include <cuda_runtime.h>
#include <cuda_fp16.h>
#include <cstdint>

#define CC       64
#define OUTC     256
#define HWN      4096
#define NCHUNK   65
#define PTILE    128
#define NTHREADS 512
#define WSTRIDE  (OUTC*CC)          // 16384 halves per weight chunk

// smem byte offsets
#define SM_XS    0                   // 64 x 128 fp32 = 32KB
#define SM_A     32768               // 2 stages x 32KB  ([256 o][64 k] f16, 128B rows)
#define SM_B     (32768 + 65536)     // 2 stages x 16KB  ([128 p][64 k] f16, 128B rows)
#define SM_TOTAL (SM_B + 32768)      // 128KB

#define SWZ(o) ((o) ^ (((o) >> 3) & 0x70))

__device__ __align__(16) __half g_Wh[NCHUNK * WSTRIDE];   // 2.1MB prepared f16 weights

__device__ __forceinline__ uint32_t s2u(const void* p) {
    uint32_t a;
    asm("{ .reg .u64 t; cvta.to.shared.u64 t, %1; cvt.u32.u64 %0, t; }" : "=r"(a) : "l"(p));
    return a;
}
__device__ __forceinline__ void cp16(uint32_t dst, const void* src) {
    asm volatile("cp.async.cg.shared.global [%0], [%1], 16;" :: "r"(dst), "l"(src) : "memory");
}
#define CP_COMMIT() asm volatile("cp.async.commit_group;" ::: "memory")
#define CP_WAIT0()  asm volatile("cp.async.wait_group 0;" ::: "memory")

__device__ __forceinline__ void ldsm_x4(uint32_t a, uint32_t& r0, uint32_t& r1, uint32_t& r2, uint32_t& r3) {
    asm volatile("ldmatrix.sync.aligned.m8n8.x4.shared.b16 {%0,%1,%2,%3}, [%4];"
                 : "=r"(r0), "=r"(r1), "=r"(r2), "=r"(r3) : "r"(a));
}
__device__ __forceinline__ void mma16816(float* d, const uint32_t* a, const uint32_t* b) {
    asm volatile("mma.sync.aligned.m16n8k16.row.col.f32.f16.f16.f32 "
                 "{%0,%1,%2,%3}, {%4,%5,%6,%7}, {%8,%9}, {%0,%1,%2,%3};"
                 : "+f"(d[0]), "+f"(d[1]), "+f"(d[2]), "+f"(d[3])
                 : "r"(a[0]), "r"(a[1]), "r"(a[2]), "r"(a[3]), "r"(b[0]), "r"(b[1]));
}

// ---- weight prep: fc_w fp32 [256 x 2144] -> g_Wh f16 [chunk][o][k], zero below diag ----
__global__ void prep_kernel(const float* __restrict__ fc_w) {
    int idx = blockIdx.x * blockDim.x + threadIdx.x;   // exactly 65*16384
    int chunk = idx >> 14;
    int rem = idx & 16383;
    int o = rem >> 6;
    int k = rem & 63;
    float v = 0.0f;
    if (chunk == 64) {
        v = fc_w[o * 2144 + k];                                // linear part
    } else if (k >= chunk) {
        int off = 64 + chunk * 64 - (chunk * (chunk - 1)) / 2 + (k - chunk);
        v = fc_w[o * 2144 + off];                              // triu(i=chunk, j=k)
    }
    g_Wh[idx] = __float2half_rn(v);
}

__device__ __forceinline__ void load_A(uint32_t dstStage, int chunk, int tid) {
    const int ks16 = (chunk < 64) ? (chunk >> 4) : 0;
    const int o = tid >> 1, h = tid & 1;
    const __half* src = g_Wh + (size_t)chunk * WSTRIDE + o * 64 + h * 8;
#pragma unroll
    for (int kt = 0; kt < 4; kt++) {
        if (kt >= ks16) {
            uint32_t d = dstStage + SWZ((uint32_t)(o * 128 + kt * 32 + h * 16));
            cp16(d, src + kt * 16);
        }
    }
}

// ---- main: 256 CTAs x 512 threads; CTA = 256 outputs x 128 pixels ----
__global__ void __launch_bounds__(NTHREADS, 1)
quad_main(const float* __restrict__ x, float* __restrict__ out) {
    extern __shared__ __align__(1024) char smem[];
    const uint32_t sb = s2u(smem);
    const int tid = threadIdx.x;
    const int lane = tid & 31;
    const int wid = tid >> 5;
    const int mw = wid & 3;          // output  64-block
    const int nw = wid >> 2;         // pixel   32-block

    const int bidx = blockIdx.x >> 5;          // batch
    const int hw0  = (blockIdx.x & 31) << 7;   // pixel tile base (128)

    float* xs = (float*)(smem + SM_XS);        // [c][p] fp32

    // prefetch A chunk 0
    load_A(sb + SM_A, 0, tid);
    CP_COMMIT();

    // load x tile [64][128]
    {
        const float4* xg = (const float4*)(x + (size_t)bidx * CC * HWN + hw0);
#pragma unroll
        for (int j = 0; j < 4; j++) {
            int idx = tid + j * NTHREADS;       // 0..2047
            int c = idx >> 5, p4 = idx & 31;
            ((float4*)xs)[c * 32 + p4] = xg[(size_t)c * (HWN / 4) + p4];
        }
    }
    __syncthreads();

    // lane-derived ldmatrix offsets
    const int arow  = (lane & 7) + ((lane >> 3) & 1) * 8;   // A: row within 16
    const int acol  = ((lane >> 4) & 1) * 16;               // A: byte offset (hi 8 halves)
    const int b4row = (lane & 7) + ((lane >> 4) & 1) * 8;   // B x4: row within 16 (n)
    const int b4col = ((lane >> 3) & 1) * 16;               // B x4: byte offset (k half)

    float acc[4][4][4];
#pragma unroll
    for (int a = 0; a < 4; a++)
#pragma unroll
        for (int b = 0; b < 4; b++)
#pragma unroll
            for (int c = 0; c < 4; c++) acc[a][b][c] = 0.0f;

    // producer mapping: lane-contiguous pixels -> conflict-free LDS
    const int bp  = tid & 127;      // producer pixel (lane = low 5 bits -> stride-1)
    const int bks = tid >> 7;       // producer k-block (uniform within warp)

#pragma unroll 1
    for (int chunk = 0; chunk < NCHUNK; chunk++) {
        const int s = chunk & 1;
        const int ks16 = (chunk < 64) ? (chunk >> 4) : 0;

        // ---- produce B[s]: [p][k] f16 products (conflict-free xs reads) ----
        if (bks >= ks16) {
            const float xi = (chunk < 64) ? xs[chunk * PTILE + bp] : 1.0f;
            __half2 h[8];
#pragma unroll
            for (int j = 0; j < 8; j++) {
                float a0 = xs[(bks * 16 + 2 * j) * PTILE + bp];
                float a1 = xs[(bks * 16 + 2 * j + 1) * PTILE + bp];
                h[j] = __floats2half2_rn(xi * a0, xi * a1);
            }
            char* bbase = smem + SM_B + s * 16384;
            const uint32_t ro = (uint32_t)bp * 128 + bks * 32;
            *(uint4*)(bbase + SWZ(ro))      = *(uint4*)&h[0];
            *(uint4*)(bbase + SWZ(ro + 16)) = *(uint4*)&h[4];
        }

        CP_WAIT0();        // A[chunk] arrived
        __syncthreads();   // A[s] + B[s] visible to all

        if (chunk + 1 < NCHUNK) {        // prefetch next A (overlaps mma below)
            load_A(sb + SM_A + (s ^ 1) * 32768, chunk + 1, tid);
            CP_COMMIT();
        }

        const uint32_t aA = sb + SM_A + s * 32768;
        const uint32_t aB = sb + SM_B + s * 16384;

#pragma unroll
        for (int kt = 0; kt < 4; kt++) {
            if (kt >= ks16) {
                uint32_t af[4][4];
#pragma unroll
                for (int mt = 0; mt < 4; mt++) {
                    uint32_t addr = aA + SWZ((uint32_t)((mw * 64 + mt * 16 + arow) * 128 + kt * 32 + acol));
                    ldsm_x4(addr, af[mt][0], af[mt][1], af[mt][2], af[mt][3]);
                }
                uint32_t bf[4][2];
#pragma unroll
                for (int nt2 = 0; nt2 < 2; nt2++) {   // x4: two n-blocks per load
                    uint32_t addr = aB + SWZ((uint32_t)((nw * 32 + nt2 * 16 + b4row) * 128 + kt * 32 + b4col));
                    ldsm_x4(addr, bf[nt2 * 2][0], bf[nt2 * 2][1], bf[nt2 * 2 + 1][0], bf[nt2 * 2 + 1][1]);
                }
#pragma unroll
                for (int mt = 0; mt < 4; mt++)
#pragma unroll
                    for (int nt = 0; nt < 4; nt++)
                        mma16816(acc[mt][nt], af[mt], bf[nt]);
            }
        }
    }

    // ---- epilogue: fp32 accumulators -> out[b][o][hw] ----
#pragma unroll
    for (int mt = 0; mt < 4; mt++) {
#pragma unroll
        for (int nt = 0; nt < 4; nt++) {
            const int o = mw * 64 + mt * 16 + (lane >> 2);
            const int p = nw * 32 + nt * 8 + (lane & 3) * 2;
            float* op = out + ((size_t)bidx * OUTC + o) * HWN + hw0 + p;
            float2 v0 = make_float2(acc[mt][nt][0], acc[mt][nt][1]);
            float2 v1 = make_float2(acc[mt][nt][2], acc[mt][nt][3]);
            *(float2*)op = v0;
            *(float2*)(op + 8 * HWN) = v1;
        }
    }
}

extern "C" void kernel_launch(void* const* d_in, const int* in_sizes, int n_in,
                              void* d_out, int out_size) {
    const float* x    = (const float*)d_in[0];
    const float* fc_w = (const float*)d_in[1];
    float* out = (float*)d_out;

    cudaFuncSetAttribute(quad_main, cudaFuncAttributeMaxDynamicSharedMemorySize, SM_TOTAL);

    prep_kernel<<<1040, 1024>>>(fc_w);            // 65*16384 threads exactly
    quad_main<<<256, NTHREADS, SM_TOTAL>>>(x, out);
}